// round 1
// baseline (speedup 1.0000x reference)
#include <cuda_runtime.h>
#include <cstdint>
#include <math.h>

#define NB 32
#define NS 512
#define NE 300
#define NHH 256
#define NT 12
#define NGATE 1024
#define TAG_START 10
#define TAG_STOP 11
#define FNEG (-10000.0f)
#define GCTA 64   // CTAs per direction in recurrence

// ---------------- scratch (static device arrays; no allocation) ----------------
static __device__ float g_gates[2u * NS * NB * NGATE];   // 128 MB: [dir][s][b][1024]
static __device__ float g_h[2u * NS * NB * NHH];         // 33.5 MB: [dir][s][b][256]
static __device__ int   g_done[2 * NS];

__device__ __forceinline__ float sigf(float x) { return 1.f / (1.f + __expf(-x)); }

// ---------------- zero the step counters (runs first each replay) ----------------
__global__ void zero_done_kernel() {
    int i = blockIdx.x * blockDim.x + threadIdx.x;
    if (i < 2 * NS) g_done[i] = 0;
}

// ---------------- Phase A: embedding gather + input GEMM ----------------
// C[m][n] = sum_e emb[tok(m)][e] * wih[n][e] + bih[n] + bhh[n],  m = s*32+b
// Tiles: BM=64, BN=64, BK=20 (300 = 15*20). 256 threads, 4x4 microtile.
__global__ void input_gemm_kernel(const int* __restrict__ inputs,
                                  const float* __restrict__ embed,
                                  const float* __restrict__ wih_f,
                                  const float* __restrict__ bih_f,
                                  const float* __restrict__ bhh_f,
                                  const float* __restrict__ wih_b,
                                  const float* __restrict__ bih_b,
                                  const float* __restrict__ bhh_b) {
    const int dir = blockIdx.z;
    const float* __restrict__ wih = dir ? wih_b : wih_f;
    const float* __restrict__ bih = dir ? bih_b : bih_f;
    const float* __restrict__ bhh = dir ? bhh_b : bhh_f;
    const int m0 = blockIdx.x * 64;
    const int n0 = blockIdx.y * 64;

    __shared__ int   tok_s[64];
    __shared__ float A_s[20][65];   // [k][m], padded
    __shared__ float W_s[20][65];   // [k][n], padded

    const int tid = threadIdx.x;
    if (tid < 64) {
        const int m = m0 + tid;
        const int s = m >> 5, b = m & 31;
        tok_s[tid] = inputs[b * NS + s];
    }

    float acc[4][4];
#pragma unroll
    for (int i = 0; i < 4; i++)
#pragma unroll
        for (int j = 0; j < 4; j++) acc[i][j] = 0.f;

    const int tn = tid & 15;   // 16 cols of threads
    const int tm = tid >> 4;   // 16 rows of threads
    __syncthreads();

    for (int kt = 0; kt < 15; kt++) {
        const int k0 = kt * 20;
        __syncthreads();
        // 640 float4 loads: 320 for A (gathered embedding rows), 320 for W
        for (int u = tid; u < 640; u += 256) {
            const int which = u >= 320;
            const int idx = which ? (u - 320) : u;
            const int row = idx / 5;
            const int c4 = idx % 5;
            const float* src = which
                ? (wih + (size_t)(n0 + row) * NE + k0 + c4 * 4)
                : (embed + (size_t)tok_s[row] * NE + k0 + c4 * 4);
            const float4 v = *(const float4*)src;
            float* dst = which ? &W_s[0][0] : &A_s[0][0];
            dst[(c4 * 4 + 0) * 65 + row] = v.x;
            dst[(c4 * 4 + 1) * 65 + row] = v.y;
            dst[(c4 * 4 + 2) * 65 + row] = v.z;
            dst[(c4 * 4 + 3) * 65 + row] = v.w;
        }
        __syncthreads();
#pragma unroll 5
        for (int kk = 0; kk < 20; kk++) {
            float a[4], w[4];
#pragma unroll
            for (int i = 0; i < 4; i++) a[i] = A_s[kk][tm * 4 + i];
#pragma unroll
            for (int j = 0; j < 4; j++) w[j] = W_s[kk][tn * 4 + j];
#pragma unroll
            for (int i = 0; i < 4; i++)
#pragma unroll
                for (int j = 0; j < 4; j++) acc[i][j] += a[i] * w[j];
        }
    }

    // epilogue: add biases, store float4 rows
    const int ncol = n0 + tn * 4;
    const float4 b1 = *(const float4*)(bih + ncol);
    const float4 b2 = *(const float4*)(bhh + ncol);
    const float4 bias = make_float4(b1.x + b2.x, b1.y + b2.y, b1.z + b2.z, b1.w + b2.w);
#pragma unroll
    for (int i = 0; i < 4; i++) {
        const int m = m0 + tm * 4 + i;
        float4 o = make_float4(acc[i][0] + bias.x, acc[i][1] + bias.y,
                               acc[i][2] + bias.z, acc[i][3] + bias.w);
        *(float4*)(g_gates + ((size_t)dir * (NS * NB) + m) * NGATE + ncol) = o;
    }
}

// ---------------- Phase B: persistent bidirectional LSTM recurrence ----------------
// grid = 128 CTAs (dir = bx>>6, cta = bx&63), block = 128 threads.
// CTA owns hidden units [cta*4, cta*4+4) => 16 whh rows resident in SMEM.
// dyn smem floats: w 4096 | h 8192 | gates 512 | c 128  => 51712 bytes
__global__ void lstm_rec_kernel(const float* __restrict__ whh_f,
                                const float* __restrict__ whh_b) {
    extern __shared__ float sm[];
    float* w_s = sm;                 // [k=256][16]
    float* h_s = sm + 4096;          // [b=32][256]
    float* g_s = sm + 4096 + 8192;   // [b=32][16]
    float* c_s = g_s + 512;          // [b=32][4]

    const int tid = threadIdx.x;
    const int dir = blockIdx.x >> 6;
    const int cta = blockIdx.x & 63;
    const int j0 = cta * 4;
    const float* __restrict__ whh = dir ? whh_b : whh_f;

    for (int idx = tid; idx < 4096; idx += 128) {
        const int k = idx >> 4, r = idx & 15;
        const int gg = r >> 2, jj = r & 3;
        w_s[idx] = whh[(size_t)(gg * NHH + j0 + jj) * NHH + k];
    }

    const int b = tid >> 2;
    const int g = tid & 3;
    const float4* w_s4 = (const float4*)w_s;
    __syncthreads();

    for (int t = 0; t < NS; t++) {
        const int s = dir ? (NS - 1 - t) : t;
        if (t > 0) {
            const int sp = dir ? (s + 1) : (s - 1);
            if (tid == 0) {
                volatile int* dp = g_done + dir * NS + sp;
                while (*dp < GCTA) {}
            }
            __syncthreads();
            const float4* src = (const float4*)(g_h + ((size_t)dir * NS + sp) * (NB * NHH));
            float4* dst = (float4*)h_s;
#pragma unroll
            for (int i = 0; i < 16; i++) dst[tid + i * 128] = __ldcg(src + tid + i * 128);
            __syncthreads();
        }

        float4 acc = make_float4(0.f, 0.f, 0.f, 0.f);
        if (t > 0) {
            const float4* hb = (const float4*)(h_s + b * NHH);
#pragma unroll 8
            for (int k4 = 0; k4 < 64; k4++) {
                const float4 hv = hb[k4];
                float4 w;
                w = w_s4[(k4 * 4 + 0) * 4 + g];
                acc.x += w.x * hv.x; acc.y += w.y * hv.x; acc.z += w.z * hv.x; acc.w += w.w * hv.x;
                w = w_s4[(k4 * 4 + 1) * 4 + g];
                acc.x += w.x * hv.y; acc.y += w.y * hv.y; acc.z += w.z * hv.y; acc.w += w.w * hv.y;
                w = w_s4[(k4 * 4 + 2) * 4 + g];
                acc.x += w.x * hv.z; acc.y += w.y * hv.z; acc.z += w.z * hv.z; acc.w += w.w * hv.z;
                w = w_s4[(k4 * 4 + 3) * 4 + g];
                acc.x += w.x * hv.w; acc.y += w.y * hv.w; acc.z += w.z * hv.w; acc.w += w.w * hv.w;
            }
        }
        const float4 gin = *(const float4*)(g_gates +
            (((size_t)dir * NS + s) * NB + b) * NGATE + g * NHH + j0);
        acc.x += gin.x; acc.y += gin.y; acc.z += gin.z; acc.w += gin.w;
        ((float4*)g_s)[b * 4 + g] = acc;
        __syncthreads();

        {
            const int bb = tid >> 2, jj = tid & 3;
            const float iv = g_s[bb * 16 + jj];
            const float fv = g_s[bb * 16 + 4 + jj];
            const float gv = g_s[bb * 16 + 8 + jj];
            const float ov = g_s[bb * 16 + 12 + jj];
            const float cp = (t == 0) ? 0.f : c_s[bb * 4 + jj];
            const float cn = sigf(fv) * cp + sigf(iv) * tanhf(gv);
            const float hn = sigf(ov) * tanhf(cn);
            c_s[bb * 4 + jj] = cn;
            g_h[(((size_t)dir * NS + s) * NB + bb) * NHH + j0 + jj] = hn;
        }
        __threadfence();
        __syncthreads();
        if (tid == 0) atomicAdd(g_done + dir * NS + s, 1);
    }
}

// ---------------- Phase C: feats + Viterbi, one CTA per batch ----------------
// dyn smem: fcw 6144f | feat 6144f | trans 144f | v 16f | bp 6144 bytes => 55936 B
__global__ void feats_viterbi_kernel(const float* __restrict__ fc_w,
                                     const float* __restrict__ fc_b,
                                     const float* __restrict__ trans,
                                     float* __restrict__ out, int out_size) {
    extern __shared__ float sm[];
    float* fcw_s = sm;                       // [12][512]
    float* feat_s = sm + 6144;               // [512][12]
    float* tr_s = sm + 12288;                // [12][12]
    float* v_s = sm + 12432;                 // [16]
    unsigned char* bp_s = (unsigned char*)(sm + 12448);  // [512][12]

    const int b = blockIdx.x;
    const int tid = threadIdx.x;          // 128
    for (int i = tid; i < 6144; i += 128) fcw_s[i] = fc_w[i];
    for (int i = tid; i < 144; i += 128) tr_s[i] = trans[i];
    __syncthreads();

    const int warp = tid >> 5, lane = tid & 31;
    // feats: each warp handles one s at a time; lane covers j = lane*8..+7 per half
    for (int s = warp; s < NS; s += 4) {
        const float4* pf = (const float4*)(g_h + ((size_t)0 * NS + s) * (NB * NHH) + b * NHH + lane * 8);
        const float4* pb = (const float4*)(g_h + ((size_t)1 * NS + s) * (NB * NHH) + b * NHH + lane * 8);
        const float4 f0 = __ldcg(pf), f1 = __ldcg(pf + 1);
        const float4 h0 = __ldcg(pb), h1 = __ldcg(pb + 1);
        for (int t = 0; t < NT; t++) {
            const float* w = fcw_s + t * 512 + lane * 8;
            const float* w2 = w + 256;
            float p = f0.x * w[0] + f0.y * w[1] + f0.z * w[2] + f0.w * w[3]
                    + f1.x * w[4] + f1.y * w[5] + f1.z * w[6] + f1.w * w[7]
                    + h0.x * w2[0] + h0.y * w2[1] + h0.z * w2[2] + h0.w * w2[3]
                    + h1.x * w2[4] + h1.y * w2[5] + h1.z * w2[6] + h1.w * w2[7];
            p += __shfl_xor_sync(0xffffffffu, p, 16);
            p += __shfl_xor_sync(0xffffffffu, p, 8);
            p += __shfl_xor_sync(0xffffffffu, p, 4);
            p += __shfl_xor_sync(0xffffffffu, p, 2);
            p += __shfl_xor_sync(0xffffffffu, p, 1);
            if (lane == 0) feat_s[s * NT + t] = p + fc_b[t];
        }
    }
    __syncthreads();

    if (warp == 0) {
        const int tl = (lane < NT) ? lane : 0;   // clamped tag id for lanes >= 12
        float v = (lane == TAG_START) ? 0.f : FNEG;
        for (int s = 0; s < NS; s++) {
            float best = -3.0e38f;
            int bestp = 0;
#pragma unroll
            for (int p = 0; p < NT; p++) {
                const float vp = __shfl_sync(0xffffffffu, v, p);
                const float sc = vp + tr_s[p * NT + tl];
                if (sc > best) { best = sc; bestp = p; }   // first-max tie-break
            }
            v = best + feat_s[s * NT + tl];
            if (lane < NT) bp_s[s * NT + lane] = (unsigned char)bestp;
        }
        if (lane < NT) v_s[lane] = v + tr_s[lane * NT + TAG_STOP];
        __syncwarp();
        if (lane == 0) {
            float best = v_s[0];
            int last = 0;
            for (int t = 1; t < NT; t++)
                if (v_s[t] > best) { best = v_s[t]; last = t; }
            if (b < out_size) out[b] = best;
            const int base = NB + b * NS;   // paths after 32 scores
            if (base + NS - 1 < out_size) out[base + NS - 1] = (float)last;
            int tag = last;
            for (int s = NS - 1; s >= 0; s--) {
                const int pv = bp_s[s * NT + tag];
                if (s >= 1 && base + s - 1 < out_size) out[base + s - 1] = (float)pv;
                tag = pv;
            }
        }
    }
}

// ---------------- launch ----------------
extern "C" void kernel_launch(void* const* d_in, const int* in_sizes, int n_in,
                              void* d_out, int out_size) {
    const int*   inputs = (const int*)d_in[0];
    const float* embed  = (const float*)d_in[1];
    const float* wih_f  = (const float*)d_in[2];
    const float* whh_f  = (const float*)d_in[3];
    const float* bih_f  = (const float*)d_in[4];
    const float* bhh_f  = (const float*)d_in[5];
    const float* wih_b  = (const float*)d_in[6];
    const float* whh_b  = (const float*)d_in[7];
    const float* bih_b  = (const float*)d_in[8];
    const float* bhh_b  = (const float*)d_in[9];
    const float* fc_w   = (const float*)d_in[10];
    const float* fc_b   = (const float*)d_in[11];
    const float* trans  = (const float*)d_in[12];

    const int lstm_smem = (4096 + 8192 + 512 + 128) * 4;         // 51712
    const int vit_smem  = 12448 * 4 + 6144;                       // 55936
    cudaFuncSetAttribute(lstm_rec_kernel, cudaFuncAttributeMaxDynamicSharedMemorySize, lstm_smem);
    cudaFuncSetAttribute(feats_viterbi_kernel, cudaFuncAttributeMaxDynamicSharedMemorySize, vit_smem);

    zero_done_kernel<<<4, 256>>>();
    input_gemm_kernel<<<dim3(256, 16, 2), 256>>>(inputs, embed,
                                                 wih_f, bih_f, bhh_f,
                                                 wih_b, bih_b, bhh_b);
    lstm_rec_kernel<<<2 * GCTA, 128, lstm_smem>>>(whh_f, whh_b);
    feats_viterbi_kernel<<<NB, 128, vit_smem>>>(fc_w, fc_b, trans, (float*)d_out, out_size);
}

// round 2
// speedup vs baseline: 1.6188x; 1.6188x over previous
#include <cuda_runtime.h>
#include <cstdint>
#include <math.h>

typedef unsigned long long ull;

#define NB 32
#define NS 512
#define NE 300
#define NHH 256
#define NT 12
#define NGATE 1024
#define TAG_START 10
#define TAG_STOP 11
#define FNEG (-10000.0f)

// ---------------- scratch (static device arrays; no allocation) ----------------
static __device__ float g_gates[2u * NS * NB * NGATE];   // [dir][m=s*32+b][1024]
static __device__ float g_h[2u * NS * NB * NHH];         // [dir][s][b][256]
static __device__ float g_feat[(size_t)NB * NS * NT];    // [b][s][12]
static __device__ int   g_done[2 * NS];

__device__ __forceinline__ float sigf(float x) { return 1.f / (1.f + __expf(-x)); }

__device__ __forceinline__ ull pack2(float lo, float hi) {
    ull r; asm("mov.b64 %0, {%1, %2};" : "=l"(r) : "f"(lo), "f"(hi)); return r;
}
__device__ __forceinline__ float2 unpack2(ull v) {
    float2 f; asm("mov.b64 {%0, %1}, %2;" : "=f"(f.x), "=f"(f.y) : "l"(v)); return f;
}
// packed dual fp32 fma: acc.lo += a.lo*b.lo ; acc.hi += a.hi*b.hi
__device__ __forceinline__ void ffma2(ull& d, ull a, ull b) {
    asm("fma.rn.f32x2 %0, %1, %2, %0;" : "+l"(d) : "l"(a), "l"(b));
}

// ---------------- zero the step counters ----------------
__global__ void zero_done_kernel() {
    int i = blockIdx.x * blockDim.x + threadIdx.x;
    if (i < 2 * NS) g_done[i] = 0;
}

// ---------------- Phase A: embedding gather + input GEMM (f32x2) ----------------
// BM=128, BN=64, BK=20. 256 threads, 8x4 microtile, k-paired accumulators.
__global__ void __launch_bounds__(256)
input_gemm_kernel(const int* __restrict__ inputs,
                  const float* __restrict__ embed,
                  const float* __restrict__ wih_f,
                  const float* __restrict__ bih_f,
                  const float* __restrict__ bhh_f,
                  const float* __restrict__ wih_b,
                  const float* __restrict__ bih_b,
                  const float* __restrict__ bhh_b) {
    const int dir = blockIdx.z;
    const float* __restrict__ wih = dir ? wih_b : wih_f;
    const float* __restrict__ bih = dir ? bih_b : bih_f;
    const float* __restrict__ bhh = dir ? bhh_b : bhh_f;
    const int n0 = blockIdx.x * 64;
    const int m0 = blockIdx.y * 128;

    __shared__ int    tok_s[128];
    __shared__ float2 A_s[10 * 128];   // [kp][m] pairs (even k, odd k)
    __shared__ float2 W_s[10 * 64];    // [kp][n]

    const int tid = threadIdx.x;
    if (tid < 128) {
        const int m = m0 + tid;
        tok_s[tid] = inputs[(m & 31) * NS + (m >> 5)];
    }
    const int tn = tid & 15;   // n-group (4 cols)
    const int tm = tid >> 4;   // m-group (8 rows)

    ull acc[8][4];
#pragma unroll
    for (int i = 0; i < 8; i++)
#pragma unroll
        for (int j = 0; j < 4; j++) acc[i][j] = 0ull;

    __syncthreads();
    for (int kt = 0; kt < 15; kt++) {
        const int k0 = kt * 20;
        __syncthreads();
        for (int u = tid; u < 960; u += 256) {
            if (u < 640) {
                const int row = u / 5, c4 = u % 5;
                const float4 v = *(const float4*)(embed + (size_t)tok_s[row] * NE + k0 + c4 * 4);
                A_s[(c4 * 2) * 128 + row]     = make_float2(v.x, v.y);
                A_s[(c4 * 2 + 1) * 128 + row] = make_float2(v.z, v.w);
            } else {
                const int idx = u - 640;
                const int n = idx / 5, c4 = idx % 5;
                const float4 v = *(const float4*)(wih + (size_t)(n0 + n) * NE + k0 + c4 * 4);
                W_s[(c4 * 2) * 64 + n]     = make_float2(v.x, v.y);
                W_s[(c4 * 2 + 1) * 64 + n] = make_float2(v.z, v.w);
            }
        }
        __syncthreads();
#pragma unroll
        for (int kp = 0; kp < 10; kp++) {
            const ulonglong2* ap = (const ulonglong2*)(A_s + kp * 128 + tm * 8);
            const ulonglong2* wp = (const ulonglong2*)(W_s + kp * 64 + tn * 4);
            const ulonglong2 a0 = ap[0], a1 = ap[1], a2 = ap[2], a3 = ap[3];
            const ulonglong2 w0 = wp[0], w1 = wp[1];
            const ull a[8] = {a0.x, a0.y, a1.x, a1.y, a2.x, a2.y, a3.x, a3.y};
            const ull w[4] = {w0.x, w0.y, w1.x, w1.y};
#pragma unroll
            for (int i = 0; i < 8; i++)
#pragma unroll
                for (int j = 0; j < 4; j++) ffma2(acc[i][j], a[i], w[j]);
        }
    }

    const int ncol = n0 + tn * 4;
    const float4 b1 = *(const float4*)(bih + ncol);
    const float4 b2 = *(const float4*)(bhh + ncol);
    const float bx = b1.x + b2.x, by = b1.y + b2.y, bz = b1.z + b2.z, bw = b1.w + b2.w;
#pragma unroll
    for (int i = 0; i < 8; i++) {
        const int m = m0 + tm * 8 + i;
        const float2 s0 = unpack2(acc[i][0]);
        const float2 s1 = unpack2(acc[i][1]);
        const float2 s2 = unpack2(acc[i][2]);
        const float2 s3 = unpack2(acc[i][3]);
        const float4 o = make_float4(s0.x + s0.y + bx, s1.x + s1.y + by,
                                     s2.x + s2.y + bz, s3.x + s3.y + bw);
        *(float4*)(g_gates + ((size_t)dir * (NS * NB) + m) * NGATE + ncol) = o;
    }
}

// ---------------- Phase B: persistent bidirectional LSTM recurrence (f32x2) ----------------
// 128 CTAs (dir = bx>>6, cta = bx&63), 128 threads. CTA owns hidden units [cta*4, cta*4+4).
// Thread = (ks = k-quarter = warp, b4 = 4-batch group, r4 = 4-row group of r=g*4+jj).
// smem: w2_s 16KB (k-paired dup-free weights) | h_s 32KB | p_s 18KB partials.
__global__ void lstm_rec_kernel(const float* __restrict__ whh_f,
                                const float* __restrict__ whh_b) {
    extern __shared__ char smraw[];
    ull*   w2_s = (ull*)smraw;                    // [kp=128][r=16]
    float* h_s  = (float*)(smraw + 16384);        // [b=32][k=256]
    ull*   p_s  = (ull*)(smraw + 49152);          // [ks=4][b=32][18] (pad 18)

    const int tid = threadIdx.x;
    const int dir = blockIdx.x >> 6;
    const int cta = blockIdx.x & 63;
    const int j0 = cta * 4;
    const float* __restrict__ whh = dir ? whh_b : whh_f;

    // repack whh rows for this CTA as (even-k, odd-k) pairs: w2_s[kp*16 + r]
    for (int idx = tid; idx < 2048; idx += 128) {
        const int kp = idx >> 4, r = idx & 15;
        const int row = (r >> 2) * NHH + j0 + (r & 3);
        const float2 wv = *(const float2*)(whh + (size_t)row * NHH + kp * 2);
        w2_s[idx] = pack2(wv.x, wv.y);
    }

    const int lane = tid & 31;
    const int ks = tid >> 5;
    const int b4 = lane >> 2, r4 = lane & 3;
    const int bb = tid >> 2, jj = tid & 3;    // activation role: (batch, j-offset)
    float c_reg = 0.f;
    const size_t hb_dir = (size_t)dir * NS * NB * NHH;
    const int dbase = dir * NS;
    __syncthreads();

    for (int t = 0; t < NS; t++) {
        const int s = dir ? (NS - 1 - t) : t;
        // prefetch gate inputs (independent of h)
        const float* gb = g_gates + (((size_t)dir * NS + s) * NB + bb) * NGATE + j0 + jj;
        float a_i = gb[0], a_f = gb[NHH], a_g = gb[2 * NHH], a_o = gb[3 * NHH];

        if (t > 0) {
            const int sp = dir ? (s + 1) : (s - 1);
            if (tid == 0) {
                volatile int* dp = g_done + dbase + sp;
                while (*dp < 64) {}
            }
            __syncthreads();
            // stage h_{t-1} into smem (coalesced, conflict-free)
            const float4* src = (const float4*)(g_h + hb_dir + (size_t)sp * (NB * NHH));
            float4* dst = (float4*)h_s;
#pragma unroll
            for (int i = 0; i < 16; i++) dst[tid + i * 128] = __ldcg(src + tid + i * 128);
            __syncthreads();

            ull acc[4][4];
#pragma unroll
            for (int bi = 0; bi < 4; bi++) {
                acc[bi][0] = 0ull; acc[bi][1] = 0ull; acc[bi][2] = 0ull; acc[bi][3] = 0ull;
            }
            const int kbase = ks * 64;
#pragma unroll 4
            for (int kk = 0; kk < 16; kk++) {
                const int k0l = kbase + kk * 4;
                const int kp0 = k0l >> 1;
                const ulonglong2 wa = *(const ulonglong2*)(w2_s + kp0 * 16 + r4 * 4);
                const ulonglong2 wb = *(const ulonglong2*)(w2_s + kp0 * 16 + r4 * 4 + 2);
                const ulonglong2 wc = *(const ulonglong2*)(w2_s + (kp0 + 1) * 16 + r4 * 4);
                const ulonglong2 wd = *(const ulonglong2*)(w2_s + (kp0 + 1) * 16 + r4 * 4 + 2);
#pragma unroll
                for (int bi = 0; bi < 4; bi++) {
                    const ulonglong2 hv = *(const ulonglong2*)(h_s + (b4 * 4 + bi) * NHH + k0l);
                    ffma2(acc[bi][0], hv.x, wa.x);
                    ffma2(acc[bi][1], hv.x, wa.y);
                    ffma2(acc[bi][2], hv.x, wb.x);
                    ffma2(acc[bi][3], hv.x, wb.y);
                    ffma2(acc[bi][0], hv.y, wc.x);
                    ffma2(acc[bi][1], hv.y, wc.y);
                    ffma2(acc[bi][2], hv.y, wd.x);
                    ffma2(acc[bi][3], hv.y, wd.y);
                }
            }
#pragma unroll
            for (int bi = 0; bi < 4; bi++) {
                ull* pp = p_s + ks * 576 + (b4 * 4 + bi) * 18 + r4 * 4;
                *(ulonglong2*)pp       = make_ulonglong2(acc[bi][0], acc[bi][1]);
                *(ulonglong2*)(pp + 2) = make_ulonglong2(acc[bi][2], acc[bi][3]);
            }
            __syncthreads();
            // reduce 4 k-quarters x 2 packed lanes per gate
            const float2* pf = (const float2*)p_s;
#pragma unroll
            for (int q = 0; q < 4; q++) {
                const int base = q * 576 + bb * 18 + jj;
                const float2 v0 = pf[base + 0];
                const float2 v1 = pf[base + 4];
                const float2 v2 = pf[base + 8];
                const float2 v3 = pf[base + 12];
                a_i += v0.x + v0.y;
                a_f += v1.x + v1.y;
                a_g += v2.x + v2.y;
                a_o += v3.x + v3.y;
            }
        }
        const float cn = sigf(a_f) * c_reg + sigf(a_i) * tanhf(a_g);
        const float hn = sigf(a_o) * tanhf(cn);
        c_reg = cn;
        g_h[hb_dir + ((size_t)s * NB + bb) * NHH + j0 + jj] = hn;
        __threadfence();
        __syncthreads();
        if (tid == 0) atomicAdd(g_done + dbase + s, 1);
    }
}

// ---------------- Phase C1: feats = hs @ fc_w^T + fc_b ----------------
// grid = 512 (one s per CTA), 256 threads (8 warps). Interleaved lane->j mapping
// (f4 = lane + 32c) keeps every LDS.128/LDG.128 conflict-free & coalesced.
__global__ void feats_kernel(const float* __restrict__ fc_w,
                             const float* __restrict__ fc_b) {
    __shared__ float fcw_s[NT * 512];
    __shared__ float fcb_s[NT];
    const int s = blockIdx.x;
    const int tid = threadIdx.x;
    for (int i = tid; i < NT * 512; i += 256) fcw_s[i] = fc_w[i];
    if (tid < NT) fcb_s[tid] = fc_b[tid];
    __syncthreads();

    const int w = tid >> 5, lane = tid & 31;
#pragma unroll
    for (int rep = 0; rep < 4; rep++) {
        const int b = w + rep * 8;
        const float4* hf = (const float4*)(g_h + ((size_t)s * NB + b) * NHH);
        const float4* hb = (const float4*)(g_h + (size_t)NS * NB * NHH + ((size_t)s * NB + b) * NHH);
        const float4 v0 = __ldcg(hf + lane);
        const float4 v1 = __ldcg(hf + lane + 32);
        const float4 v2 = __ldcg(hb + lane);
        const float4 v3 = __ldcg(hb + lane + 32);
#pragma unroll
        for (int tt = 0; tt < NT; tt++) {
            const float4* wr = (const float4*)(fcw_s + tt * 512);
            const float4 w0 = wr[lane];
            const float4 w1 = wr[lane + 32];
            const float4 w2 = wr[lane + 64];
            const float4 w3 = wr[lane + 96];
            float p = v0.x * w0.x + v0.y * w0.y + v0.z * w0.z + v0.w * w0.w
                    + v1.x * w1.x + v1.y * w1.y + v1.z * w1.z + v1.w * w1.w
                    + v2.x * w2.x + v2.y * w2.y + v2.z * w2.z + v2.w * w2.w
                    + v3.x * w3.x + v3.y * w3.y + v3.z * w3.z + v3.w * w3.w;
            p += __shfl_xor_sync(0xffffffffu, p, 16);
            p += __shfl_xor_sync(0xffffffffu, p, 8);
            p += __shfl_xor_sync(0xffffffffu, p, 4);
            p += __shfl_xor_sync(0xffffffffu, p, 2);
            p += __shfl_xor_sync(0xffffffffu, p, 1);
            if (lane == 0) g_feat[((size_t)b * NS + s) * NT + tt] = p + fcb_s[tt];
        }
    }
}

// ---------------- Phase C2: Viterbi, one warp per batch ----------------
__global__ void viterbi_kernel(const float* __restrict__ trans,
                               float* __restrict__ out, int out_size) {
    __shared__ float feat_s[NS * NT];
    __shared__ unsigned char bp_s[NS * NT];
    __shared__ float term_s[NT];
    const int b = blockIdx.x;
    const int lane = threadIdx.x;  // 32

    const float4* src = (const float4*)(g_feat + (size_t)b * NS * NT);
    float4* dst = (float4*)feat_s;
    for (int i = lane; i < (NS * NT) / 4; i += 32) dst[i] = __ldcg(src + i);

    const int tl = (lane < NT) ? lane : (NT - 1);
    float tr_reg[NT];
#pragma unroll
    for (int p = 0; p < NT; p++) tr_reg[p] = trans[p * NT + tl];
    const float tr_stop = trans[tl * NT + TAG_STOP];
    __syncwarp();

    float v = (lane == TAG_START) ? 0.f : FNEG;
    for (int s = 0; s < NS; s++) {
        float best = -3.0e38f;
        int bpi = 0;
#pragma unroll
        for (int p = 0; p < NT; p++) {
            const float sc = __shfl_sync(0xffffffffu, v, p) + tr_reg[p];
            if (sc > best) { best = sc; bpi = p; }   // first-max tie-break
        }
        v = best + feat_s[s * NT + tl];
        if (lane < NT) bp_s[s * NT + lane] = (unsigned char)bpi;
    }
    if (lane < NT) term_s[lane] = v + tr_stop;
    __syncwarp();
    if (lane == 0) {
        float best = term_s[0];
        int last = 0;
#pragma unroll
        for (int tt = 1; tt < NT; tt++)
            if (term_s[tt] > best) { best = term_s[tt]; last = tt; }
        if (b < out_size) out[b] = best;
        const int base = NB + b * NS;
        if (base + NS - 1 < out_size) out[base + NS - 1] = (float)last;
        int tag = last;
        for (int s = NS - 1; s >= 0; s--) {
            const int pv = bp_s[s * NT + tag];
            if (s >= 1 && base + s - 1 < out_size) out[base + s - 1] = (float)pv;
            tag = pv;
        }
    }
}

// ---------------- launch ----------------
extern "C" void kernel_launch(void* const* d_in, const int* in_sizes, int n_in,
                              void* d_out, int out_size) {
    const int*   inputs = (const int*)d_in[0];
    const float* embed  = (const float*)d_in[1];
    const float* wih_f  = (const float*)d_in[2];
    const float* whh_f  = (const float*)d_in[3];
    const float* bih_f  = (const float*)d_in[4];
    const float* bhh_f  = (const float*)d_in[5];
    const float* wih_b  = (const float*)d_in[6];
    const float* whh_b  = (const float*)d_in[7];
    const float* bih_b  = (const float*)d_in[8];
    const float* bhh_b  = (const float*)d_in[9];
    const float* fc_w   = (const float*)d_in[10];
    const float* fc_b   = (const float*)d_in[11];
    const float* trans  = (const float*)d_in[12];

    const int lstm_smem = 16384 + 32768 + 4 * 576 * 8;   // 67584 bytes
    cudaFuncSetAttribute(lstm_rec_kernel, cudaFuncAttributeMaxDynamicSharedMemorySize, lstm_smem);

    zero_done_kernel<<<4, 256>>>();
    input_gemm_kernel<<<dim3(16, 128, 2), 256>>>(inputs, embed,
                                                 wih_f, bih_f, bhh_f,
                                                 wih_b, bih_b, bhh_b);
    lstm_rec_kernel<<<128, 128, lstm_smem>>>(whh_f, whh_b);
    feats_kernel<<<NS, 256>>>(fc_w, fc_b);
    viterbi_kernel<<<NB, 32>>>(trans, (float*)d_out, out_size);
}